// round 2
// baseline (speedup 1.0000x reference)
#include <cuda_runtime.h>
#include <math.h>

// Problem constants
#define Nn   100
#define Cc   32
#define Hh   512
#define Tt   64
#define Bb   16
#define Ee   2000
#define HOR  10
#define BN   1600
#define NC   3200
#define G4   2048
#define MROWS 1024
#define TOTF (Tt*BN)

typedef unsigned long long ull;

// ---------------- scratch (static device memory; no allocation) ----------------
__device__ float g_X0[Tt*Bb*NC];
__device__ float g_Z[2][MROWS*G4];
__device__ float g_HS0[Tt*Bb*Hh];
__device__ float g_part[12*Bb*G4];
__device__ float g_state[8*Bb*Hh];
__device__ float g_pred[BN];
__device__ float g_xin[Bb*NC];
__device__ float g_norm[Ee];
__device__ int   g_csr_eid[Ee];
__device__ int   g_csr_off[Nn+1];

// ---------------- helpers ----------------
__device__ __forceinline__ float sigf(float x){ return 1.0f/(1.0f+expf(-x)); }
__device__ __forceinline__ float geluf(float x){
    return 0.5f*x*(1.0f+erff(x*0.70710678118654752440f));
}
__device__ __forceinline__ ull pk2(float lo, float hi){
    ull r; asm("mov.b64 %0,{%1,%2};" : "=l"(r) : "f"(lo), "f"(hi)); return r;
}
__device__ __forceinline__ ull fma2(ull a, ull b, ull c){
    ull d; asm("fma.rn.f32x2 %0, %1, %2, %3;" : "=l"(d) : "l"(a), "l"(b), "l"(c)); return d;
}
__device__ __forceinline__ float2 upk(ull v){
    float2 f; asm("mov.b64 {%0,%1}, %2;" : "=f"(f.x), "=f"(f.y) : "l"(v)); return f;
}

// ---------------- CSR + normalization (fully deterministic, one block) ----------------
__global__ void build_csr(const int* __restrict__ ei, const float* __restrict__ attr){
    __shared__ int   cols[Ee];
    __shared__ float attrs[Ee];
    __shared__ float deg[Nn];
    __shared__ float dinv[Nn];
    __shared__ int   cnt[Nn];
    __shared__ int   offs[Nn+1];
    int tid = threadIdx.x;
    for (int e = tid; e < Ee; e += blockDim.x){
        cols[e]  = ei[Ee + e];
        attrs[e] = attr[e];
    }
    __syncthreads();
    for (int d = tid; d < Nn; d += blockDim.x){
        float dg = 0.f; int c = 0;
        for (int e = 0; e < Ee; e++){
            if (cols[e] == d){ dg += attrs[e]; c++; }
        }
        deg[d] = dg; cnt[d] = c;
        dinv[d] = (dg > 0.f) ? (1.0f/sqrtf(fmaxf(dg, 1e-12f))) : 0.f;
    }
    __syncthreads();
    for (int e = tid; e < Ee; e += blockDim.x)
        g_norm[e] = dinv[ei[e]] * attrs[e] * dinv[cols[e]];
    if (tid == 0){
        offs[0] = 0;
        for (int i = 0; i < Nn; i++) offs[i+1] = offs[i] + cnt[i];
    }
    __syncthreads();
    for (int i = tid; i <= Nn; i += blockDim.x) g_csr_off[i] = offs[i];
    for (int d = tid; d < Nn; d += blockDim.x){
        int p = offs[d];
        for (int e = 0; e < Ee; e++)
            if (cols[e] == d) g_csr_eid[p++] = e;
    }
}

// ---------------- fused temporal ARMA -> gelu -> embed -> transpose ----------------
__global__ void fused_x0(const float* __restrict__ x, const int* __restrict__ ei,
                         const float* __restrict__ tw, const float* __restrict__ tv,
                         const float* __restrict__ tb, const float* __restrict__ Wemb){
    int f = blockIdx.x*blockDim.x + threadIdx.x;
    if (f >= TOTF) return;
    int tc = f / BN; int r = f - tc*BN; int bq = r / Nn; int d = r - bq*Nn;
    int base = tc*BN + bq*Nn;
    float agg = 0.f;
    int i0 = g_csr_off[d], i1 = g_csr_off[d+1];
    for (int ii = i0; ii < i1; ii++){
        int e = g_csr_eid[ii];
        agg += g_norm[e] * x[base + ei[e]];
    }
    float xi = x[f];
    int bo = f / (Nn*Tt); int rr = f - bo*(Nn*Tt); int nn = rr / Tt; int t = rr - nn*Tt;
    float* dst = g_X0 + ((size_t)(t*Bb + bo))*NC + nn*Cc;
    #pragma unroll
    for (int c2 = 0; c2 < Cc; c2++){
        float z = agg*tw[c2] + xi*tv[c2] + tb[c2];
        dst[c2] = geluf(z) + Wemb[nn*Cc + c2];
    }
}

// ---------------- big input-projection GEMM (FFMA2): C = A @ W^T + b1 + b2 ----------------
__global__ __launch_bounds__(256) void sgemm_tn(const float* __restrict__ W,
        const float* __restrict__ b1, const float* __restrict__ b2, int which){
    const int K = which ? Hh : NC;
    const float* A = which ? g_HS0 : g_X0;
    float* C = g_Z[which];
    __shared__ __align__(16) float As[8][128];
    __shared__ __align__(16) float Bs[8][128];
    int tid = threadIdx.x;
    int m0 = blockIdx.y*128, n0 = blockIdx.x*128;
    int lr = tid >> 1, lc = (tid & 1)*4;
    const float* Ap = A + (size_t)(m0 + lr)*K + lc;
    const float* Wp = W + (size_t)(n0 + lr)*K + lc;
    int tx = tid & 15, ty = tid >> 4;
    ull acc2[8][4];
    #pragma unroll
    for (int i = 0; i < 8; i++)
        #pragma unroll
        for (int j = 0; j < 4; j++) acc2[i][j] = 0ULL;

    for (int k0 = 0; k0 < K; k0 += 8){
        float4 av = *(const float4*)(Ap + k0);
        float4 wv = *(const float4*)(Wp + k0);
        As[lc+0][lr] = av.x; As[lc+1][lr] = av.y; As[lc+2][lr] = av.z; As[lc+3][lr] = av.w;
        Bs[lc+0][lr] = wv.x; Bs[lc+1][lr] = wv.y; Bs[lc+2][lr] = wv.z; Bs[lc+3][lr] = wv.w;
        __syncthreads();
        #pragma unroll
        for (int kk = 0; kk < 8; kk++){
            float a[8];
            *(float4*)(a)   = *(const float4*)&As[kk][ty*8];
            *(float4*)(a+4) = *(const float4*)&As[kk][ty*8+4];
            ulonglong2 bv0 = *(const ulonglong2*)&Bs[kk][tx*8];
            ulonglong2 bv1 = *(const ulonglong2*)&Bs[kk][tx*8+4];
            ull bb[4] = {bv0.x, bv0.y, bv1.x, bv1.y};
            #pragma unroll
            for (int i = 0; i < 8; i++){
                ull a2 = pk2(a[i], a[i]);
                #pragma unroll
                for (int j = 0; j < 4; j++)
                    acc2[i][j] = fma2(a2, bb[j], acc2[i][j]);
            }
        }
        __syncthreads();
    }
    #pragma unroll
    for (int i = 0; i < 8; i++){
        int m = m0 + ty*8 + i;
        #pragma unroll
        for (int j = 0; j < 4; j++){
            float2 v = upk(acc2[i][j]);
            int n = n0 + tx*8 + j*2;
            C[(size_t)m*G4 + n]     = v.x + b1[n]   + b2[n];
            C[(size_t)m*G4 + n + 1] = v.y + b1[n+1] + b2[n+1];
        }
    }
}

// ---------------- K-split partial GEMM (FFMA2): part[kc][b][j] = sum_k A[b][k]*W[j][k] ----
// asel: 0=h0 1=h1 2=hd1 3=hd2 4=g_xin.
__global__ __launch_bounds__(128) void gemm_part(const float* __restrict__ W,
        int asel, int ksz, int kcoff){
    extern __shared__ __align__(16) float As[];   // [ksz][16]
    int tid = threadIdx.x;
    int j  = blockIdx.x*128 + tid;
    int kc = blockIdx.y;
    const float* A; int lda;
    if      (asel == 0){ A = g_state + 0*8192;  lda = Hh; }
    else if (asel == 1){ A = g_state + 2*8192;  lda = Hh; }
    else if (asel == 2){ A = g_state + 4*8192;  lda = Hh; }
    else if (asel == 3){ A = g_state + 6*8192;  lda = Hh; }
    else               { A = g_xin;             lda = NC; }
    int kb = kc*ksz;
    for (int i = tid; i < ksz*16; i += 128){
        int k = i >> 4, b = i & 15;
        As[k*16 + b] = A[b*lda + kb + k];
    }
    __syncthreads();
    ull acc2[8];
    #pragma unroll
    for (int m = 0; m < 8; m++) acc2[m] = 0ULL;
    const float* wr = W + (size_t)j*lda + kb;
    for (int k = 0; k < ksz; k += 4){
        float4 w4 = *(const float4*)(wr + k);
        float wv[4] = {w4.x, w4.y, w4.z, w4.w};
        #pragma unroll
        for (int kk = 0; kk < 4; kk++){
            ull w2 = pk2(wv[kk], wv[kk]);
            const ulonglong2* hp = (const ulonglong2*)(As + (k+kk)*16);
            ulonglong2 h0 = hp[0], h1 = hp[1], h2 = hp[2], h3 = hp[3];
            acc2[0] = fma2(w2, h0.x, acc2[0]);
            acc2[1] = fma2(w2, h0.y, acc2[1]);
            acc2[2] = fma2(w2, h1.x, acc2[2]);
            acc2[3] = fma2(w2, h1.y, acc2[3]);
            acc2[4] = fma2(w2, h2.x, acc2[4]);
            acc2[5] = fma2(w2, h2.y, acc2[5]);
            acc2[6] = fma2(w2, h3.x, acc2[6]);
            acc2[7] = fma2(w2, h3.y, acc2[7]);
        }
    }
    float* p = g_part + (size_t)(kcoff + kc)*(Bb*G4);
    #pragma unroll
    for (int m = 0; m < 8; m++){
        float2 v = upk(acc2[m]);
        p[(2*m  )*G4 + j] = v.x;
        p[(2*m+1)*G4 + j] = v.y;
    }
}

// ---------------- LSTM activation + state update ----------------
__global__ void lstm_update(const float* __restrict__ b1, const float* __restrict__ b2,
                            int zsel, int t, int nsplit, int hsel, int store_hs){
    int idx = blockIdx.x*blockDim.x + threadIdx.x;
    if (idx >= Bb*Hh) return;
    int b = idx >> 9, u = idx & 511;
    float* h = g_state + hsel*2*8192;
    float* c = h + 8192;
    const float* Z = (zsel >= 0) ? (g_Z[zsel] + (size_t)t*Bb*G4) : nullptr;
    float pre[4];
    #pragma unroll
    for (int g = 0; g < 4; g++){
        int j = g*512 + u;
        float p = Z ? Z[b*G4 + j] : (b1[j] + b2[j]);
        for (int kc = 0; kc < nsplit; kc++)
            p += g_part[(size_t)kc*(Bb*G4) + b*G4 + j];
        pre[g] = p;
    }
    float ig = sigf(pre[0]);
    float fg = sigf(pre[1]);
    float gg = tanhf(pre[2]);
    float og = sigf(pre[3]);
    float cn = fg*c[idx] + ig*gg;
    float hn = og*tanhf(cn);
    c[idx] = cn; h[idx] = hn;
    if (store_hs) g_HS0[(size_t)t*Bb*Hh + idx] = hn;
}

__global__ void zero_states(){
    int idx = blockIdx.x*blockDim.x + threadIdx.x;
    if (idx < 4*8192) g_state[idx] = 0.f;
}

__global__ void seed_states(){
    int idx = blockIdx.x*blockDim.x + threadIdx.x;
    if (idx >= 8192) return;
    float h0f = g_state[0*8192 + idx];
    float h1f = g_state[2*8192 + idx];
    g_state[4*8192 + idx] = h0f;
    g_state[5*8192 + idx] = h0f;
    g_state[6*8192 + idx] = h1f;
    g_state[7*8192 + idx] = h1f;
}

__global__ void pred_step(const float* __restrict__ Wpw, const float* __restrict__ bp,
                          float* __restrict__ out, int step){
    int idx = blockIdx.x*blockDim.x + threadIdx.x;
    if (idx >= BN) return;
    int b = idx / Nn, nn = idx - b*Nn;
    const float* hrow = g_state + 6*8192 + b*Hh;
    const float* wrow = Wpw + nn*Hh;
    float acc = 0.f;
    for (int k = 0; k < Hh; k += 4){
        float4 hv = *(const float4*)(hrow + k);
        float4 wv = *(const float4*)(wrow + k);
        acc += hv.x*wv.x + hv.y*wv.y + hv.z*wv.z + hv.w*wv.w;
    }
    acc += bp[nn];
    g_pred[idx] = acc;
    out[idx*HOR + step] = acc;
}

__global__ void fused_xin(const int* __restrict__ ei, const float* __restrict__ gw,
        const float* __restrict__ gv, const float* __restrict__ gb,
        const float* __restrict__ Wemb){
    int idx = blockIdx.x*blockDim.x + threadIdx.x;
    if (idx >= BN) return;
    int b = idx / Nn, d = idx - b*Nn;
    float agg = 0.f;
    int i0 = g_csr_off[d], i1 = g_csr_off[d+1];
    for (int ii = i0; ii < i1; ii++){
        int e = g_csr_eid[ii];
        agg += g_norm[e] * g_pred[b*Nn + ei[e]];
    }
    float p = g_pred[idx];
    float* dst = g_xin + b*NC + d*Cc;
    #pragma unroll
    for (int c2 = 0; c2 < Cc; c2++){
        float z = agg*gw[c2] + p*gv[c2] + gb[c2];
        dst[c2] = geluf(z) + Wemb[d*Cc + c2];
    }
}

// ---------------- launch ----------------
extern "C" void kernel_launch(void* const* d_in, const int* in_sizes, int n_in,
                              void* d_out, int out_size){
    const float* window = (const float*)d_in[0];
    const int*   ei     = (const int*)  d_in[1];
    const float* eattr  = (const float*)d_in[2];
    const float* Wemb   = (const float*)d_in[3];
    const float* tgw    = (const float*)d_in[4];
    const float* tgv    = (const float*)d_in[5];
    const float* tgb    = (const float*)d_in[6];
    const float* gnw    = (const float*)d_in[7];
    const float* gnv    = (const float*)d_in[8];
    const float* gnb    = (const float*)d_in[9];
    const float* Wih0   = (const float*)d_in[10];
    const float* Whh0   = (const float*)d_in[11];
    const float* bih0   = (const float*)d_in[12];
    const float* bhh0   = (const float*)d_in[13];
    const float* Wih1   = (const float*)d_in[14];
    const float* Whh1   = (const float*)d_in[15];
    const float* bih1   = (const float*)d_in[16];
    const float* bhh1   = (const float*)d_in[17];
    const float* c1Wih  = (const float*)d_in[18];
    const float* c1Whh  = (const float*)d_in[19];
    const float* c1bih  = (const float*)d_in[20];
    const float* c1bhh  = (const float*)d_in[21];
    const float* c2Wih  = (const float*)d_in[22];
    const float* c2Whh  = (const float*)d_in[23];
    const float* c2bih  = (const float*)d_in[24];
    const float* c2bhh  = (const float*)d_in[25];
    const float* Wp     = (const float*)d_in[26];
    const float* bp     = (const float*)d_in[27];
    float* out = (float*)d_out;

    build_csr<<<1,128>>>(ei, eattr);
    fused_x0<<<TOTF/128,128>>>(window, ei, tgw, tgv, tgb, Wemb);
    sgemm_tn<<<dim3(16,8),256>>>(Wih0, bih0, bhh0, 0);   // Z0 (K=3200)
    zero_states<<<128,256>>>();

    // encoder layer 0
    for (int t = 0; t < Tt; t++){
        gemm_part<<<dim3(16,8),128, 64*16*4>>>(Whh0, 0, 64, 0);
        lstm_update<<<32,256>>>(nullptr, nullptr, 0, t, 8, 0, 1);
    }
    sgemm_tn<<<dim3(16,8),256>>>(Wih1, bih1, bhh1, 1);   // Z1 (K=512)
    // encoder layer 1
    for (int t = 0; t < Tt; t++){
        gemm_part<<<dim3(16,8),128, 64*16*4>>>(Whh1, 1, 64, 0);
        lstm_update<<<32,256>>>(nullptr, nullptr, 1, t, 8, 1, 0);
    }
    seed_states<<<32,256>>>();

    // decoder
    for (int s = 0; s < HOR; s++){
        pred_step<<<13,128>>>(Wp, bp, out, s);
        fused_xin<<<13,128>>>(ei, gnw, gnv, gnb, Wemb);
        gemm_part<<<dim3(16,8),128, 400*16*4>>>(c1Wih, 4, 400, 0);
        gemm_part<<<dim3(16,4),128, 128*16*4>>>(c1Whh, 2, 128, 8);
        lstm_update<<<32,256>>>(c1bih, c1bhh, -1, 0, 12, 2, 0);
        gemm_part<<<dim3(16,4),128, 128*16*4>>>(c2Wih, 2, 128, 0);
        gemm_part<<<dim3(16,4),128, 128*16*4>>>(c2Whh, 3, 128, 4);
        lstm_update<<<32,256>>>(c2bih, c2bhh, -1, 0, 8, 3, 0);
    }
}

// round 4
// speedup vs baseline: 1.1843x; 1.1843x over previous
#include <cuda_runtime.h>
#include <math.h>

// Problem constants
#define Nn   100
#define Cc   32
#define Hh   512
#define Tt   64
#define Bb   16
#define Ee   2000
#define HOR  10
#define BN   1600
#define NC   3200
#define G4   2048
#define TOTF (Tt*BN)
#define NBLK 128

typedef unsigned long long ull;

// ---------------- scratch (static device memory; no allocation) ----------------
__device__ float g_X0[Tt*Bb*NC];
__device__ float g_Z0[Tt*Bb*G4];
__device__ float g_Z1[Tt*Bb*G4];
__device__ float g_HS0[Tt*Bb*Hh];
__device__ float g_pp[32*Bb*G4];
__device__ float g_state[8*Bb*Hh];
__device__ float g_pred[BN];
__device__ float g_xin[Bb*NC];
__device__ float g_norm[Ee];
__device__ int   g_csr_eid[Ee];
__device__ int   g_csr_off[Nn+1];
__device__ unsigned g_cnt = 0;
__device__ unsigned g_gen = 0;

// ---------------- helpers ----------------
__device__ __forceinline__ float sigf(float x){ return 1.0f/(1.0f+expf(-x)); }
__device__ __forceinline__ float geluf(float x){
    return 0.5f*x*(1.0f+erff(x*0.70710678118654752440f));
}
__device__ __forceinline__ ull pk2(float lo, float hi){
    ull r; asm("mov.b64 %0,{%1,%2};" : "=l"(r) : "f"(lo), "f"(hi)); return r;
}
__device__ __forceinline__ ull fma2(ull a, ull b, ull c){
    ull d; asm("fma.rn.f32x2 %0, %1, %2, %3;" : "=l"(d) : "l"(a), "l"(b), "l"(c)); return d;
}
__device__ __forceinline__ float2 upk(ull v){
    float2 f; asm("mov.b64 {%0,%1}, %2;" : "=f"(f.x), "=f"(f.y) : "l"(v)); return f;
}

// software grid barrier (all NBLK blocks co-resident: NBLK=128 <= 148 SMs, 1 block/SM)
__device__ __forceinline__ void gsync(){
    __syncthreads();
    if (threadIdx.x == 0){
        __threadfence();
        unsigned gen = *(volatile unsigned*)&g_gen;
        if (atomicAdd(&g_cnt, 1u) == NBLK-1u){
            g_cnt = 0;
            __threadfence();
            *(volatile unsigned*)&g_gen = gen + 1u;
        } else {
            while (*(volatile unsigned*)&g_gen == gen) { }
        }
        __threadfence();
    }
    __syncthreads();
}

// ---------------- CSR + normalization (deterministic, one block) ----------------
__global__ void build_csr(const int* __restrict__ ei, const float* __restrict__ attr){
    __shared__ int   cols[Ee];
    __shared__ float attrs[Ee];
    __shared__ float dinv[Nn];
    __shared__ int   cnt[Nn];
    __shared__ int   offs[Nn+1];
    int tid = threadIdx.x;
    for (int e = tid; e < Ee; e += blockDim.x){
        cols[e]  = ei[Ee + e];
        attrs[e] = attr[e];
    }
    __syncthreads();
    for (int d = tid; d < Nn; d += blockDim.x){
        float dg = 0.f; int c = 0;
        for (int e = 0; e < Ee; e++){
            if (cols[e] == d){ dg += attrs[e]; c++; }
        }
        cnt[d] = c;
        dinv[d] = (dg > 0.f) ? (1.0f/sqrtf(fmaxf(dg, 1e-12f))) : 0.f;
    }
    __syncthreads();
    for (int e = tid; e < Ee; e += blockDim.x)
        g_norm[e] = dinv[ei[e]] * attrs[e] * dinv[cols[e]];
    if (tid == 0){
        offs[0] = 0;
        for (int i = 0; i < Nn; i++) offs[i+1] = offs[i] + cnt[i];
    }
    __syncthreads();
    for (int i = tid; i <= Nn; i += blockDim.x) g_csr_off[i] = offs[i];
    for (int d = tid; d < Nn; d += blockDim.x){
        int p = offs[d];
        for (int e = 0; e < Ee; e++)
            if (cols[e] == d) g_csr_eid[p++] = e;
    }
}

// ---------------- fused temporal ARMA -> gelu -> embed -> transpose ----------------
__global__ void fused_x0(const float* __restrict__ x, const int* __restrict__ ei,
                         const float* __restrict__ tw, const float* __restrict__ tv,
                         const float* __restrict__ tb, const float* __restrict__ Wemb){
    int f = blockIdx.x*blockDim.x + threadIdx.x;
    if (f >= TOTF) return;
    int tc = f / BN; int r = f - tc*BN; int bq = r / Nn; int d = r - bq*Nn;
    int base = tc*BN + bq*Nn;
    float agg = 0.f;
    int i0 = g_csr_off[d], i1 = g_csr_off[d+1];
    for (int ii = i0; ii < i1; ii++){
        int e = g_csr_eid[ii];
        agg += g_norm[e] * x[base + ei[e]];
    }
    float xi = x[f];
    int bo = f / (Nn*Tt); int rr = f - bo*(Nn*Tt); int nn = rr / Tt; int t = rr - nn*Tt;
    float* dst = g_X0 + ((size_t)(t*Bb + bo))*NC + nn*Cc;
    #pragma unroll
    for (int c2 = 0; c2 < Cc; c2++){
        float z = agg*tw[c2] + xi*tv[c2] + tb[c2];
        dst[c2] = geluf(z) + Wemb[nn*Cc + c2];
    }
}

// ---------------- Z0 GEMM (FFMA2): g_Z0 = g_X0 @ Wih0^T + bih0 + bhh0 ----------------
__global__ __launch_bounds__(256) void sgemm_z0(const float* __restrict__ W,
        const float* __restrict__ b1, const float* __restrict__ b2){
    const int K = NC;
    __shared__ __align__(16) float As[8][128];
    __shared__ __align__(16) float Bs[8][128];
    int tid = threadIdx.x;
    int m0 = blockIdx.y*128, n0 = blockIdx.x*128;
    int lr = tid >> 1, lc = (tid & 1)*4;
    const float* Ap = g_X0 + (size_t)(m0 + lr)*K + lc;
    const float* Wp = W + (size_t)(n0 + lr)*K + lc;
    int tx = tid & 15, ty = tid >> 4;
    ull acc2[8][4];
    #pragma unroll
    for (int i = 0; i < 8; i++)
        #pragma unroll
        for (int j = 0; j < 4; j++) acc2[i][j] = 0ULL;

    for (int k0 = 0; k0 < K; k0 += 8){
        float4 av = *(const float4*)(Ap + k0);
        float4 wv = *(const float4*)(Wp + k0);
        As[lc+0][lr] = av.x; As[lc+1][lr] = av.y; As[lc+2][lr] = av.z; As[lc+3][lr] = av.w;
        Bs[lc+0][lr] = wv.x; Bs[lc+1][lr] = wv.y; Bs[lc+2][lr] = wv.z; Bs[lc+3][lr] = wv.w;
        __syncthreads();
        #pragma unroll
        for (int kk = 0; kk < 8; kk++){
            float a[8];
            *(float4*)(a)   = *(const float4*)&As[kk][ty*8];
            *(float4*)(a+4) = *(const float4*)&As[kk][ty*8+4];
            ulonglong2 bv0 = *(const ulonglong2*)&Bs[kk][tx*8];
            ulonglong2 bv1 = *(const ulonglong2*)&Bs[kk][tx*8+4];
            ull bb[4] = {bv0.x, bv0.y, bv1.x, bv1.y};
            #pragma unroll
            for (int i = 0; i < 8; i++){
                ull a2 = pk2(a[i], a[i]);
                #pragma unroll
                for (int j = 0; j < 4; j++)
                    acc2[i][j] = fma2(a2, bb[j], acc2[i][j]);
            }
        }
        __syncthreads();
    }
    #pragma unroll
    for (int i = 0; i < 8; i++){
        int m = m0 + ty*8 + i;
        #pragma unroll
        for (int j = 0; j < 4; j++){
            float2 v = upk(acc2[i][j]);
            int n = n0 + tx*8 + j*2;
            g_Z0[(size_t)m*G4 + n]     = v.x + b1[n]   + b2[n];
            g_Z0[(size_t)m*G4 + n + 1] = v.y + b1[n+1] + b2[n+1];
        }
    }
}

// ---------------- persistent-kernel phases ----------------
// K-split partial GEMM: pp[kcoff+kc][b][j] = sum_{k in chunk} A[b][k]*W[j][k]
// block mapping: jt = bid&7 (256 j each), kc = bid>>3 (16 chunks)
__device__ __forceinline__ void gemm_phase(float* sm, const float* __restrict__ W,
        const float* __restrict__ A, int lda, int ksz, int kcoff){
    int tid = threadIdx.x, bid = blockIdx.x;
    int jt = bid & 7, kc = bid >> 3;
    int j = jt*256 + tid;
    int kb = kc*ksz;
    for (int i = tid; i < ksz*16; i += 256){
        int k = i >> 4, b = i & 15;
        sm[k*16 + b] = A[b*lda + kb + k];
    }
    __syncthreads();
    ull acc2[8];
    #pragma unroll
    for (int m = 0; m < 8; m++) acc2[m] = 0ULL;
    const float* wr = W + (size_t)j*lda + kb;
    for (int k = 0; k < ksz; k += 4){
        float4 w4 = *(const float4*)(wr + k);
        float wv[4] = {w4.x, w4.y, w4.z, w4.w};
        #pragma unroll
        for (int kk = 0; kk < 4; kk++){
            ull w2 = pk2(wv[kk], wv[kk]);
            const ulonglong2* hp = (const ulonglong2*)(sm + (k+kk)*16);
            ulonglong2 h0 = hp[0], h1 = hp[1], h2 = hp[2], h3 = hp[3];
            acc2[0] = fma2(w2, h0.x, acc2[0]);
            acc2[1] = fma2(w2, h0.y, acc2[1]);
            acc2[2] = fma2(w2, h1.x, acc2[2]);
            acc2[3] = fma2(w2, h1.y, acc2[3]);
            acc2[4] = fma2(w2, h2.x, acc2[4]);
            acc2[5] = fma2(w2, h2.y, acc2[5]);
            acc2[6] = fma2(w2, h3.x, acc2[6]);
            acc2[7] = fma2(w2, h3.y, acc2[7]);
        }
    }
    float* p = g_pp + (size_t)(kcoff + kc)*(Bb*G4);
    #pragma unroll
    for (int m = 0; m < 8; m++){
        float2 v = upk(acc2[m]);
        p[(2*m  )*G4 + j] = v.x;
        p[(2*m+1)*G4 + j] = v.y;
    }
    __syncthreads();
}

// reduce partials + activation. block mapping: bb = bid>>3 (batch), ur = bid&7 (64-u range)
__device__ __forceinline__ void reduce_phase(float* sm, const float* __restrict__ Z,
        const float* __restrict__ b1, const float* __restrict__ b2, int nsplit,
        float* __restrict__ h, float* __restrict__ c, float* __restrict__ hs){
    int tid = threadIdx.x, bid = blockIdx.x;
    int g = tid >> 6, uo = tid & 63;
    int bb = bid >> 3, ur = bid & 7;
    int u = ur*64 + uo;
    int j = g*512 + u;
    float p = Z ? Z[bb*G4 + j] : (b1[j] + b2[j]);
    for (int kc = 0; kc < nsplit; kc++)
        p += g_pp[(size_t)kc*(Bb*G4) + bb*G4 + j];
    sm[g*64 + uo] = p;
    __syncthreads();
    if (tid < 64){
        int idx = bb*Hh + ur*64 + tid;
        float ig = sigf(sm[tid]);
        float fg = sigf(sm[64 + tid]);
        float gg = tanhf(sm[128 + tid]);
        float og = sigf(sm[192 + tid]);
        float cn = fg*c[idx] + ig*gg;
        float hn = og*tanhf(cn);
        c[idx] = cn; h[idx] = hn;
        if (hs) hs[idx] = hn;
    }
    __syncthreads();
}

// Z1 = HS0(1024x512) @ Wih1^T(2048x512) + biases, 128x128 tiles over 128 blocks
__device__ void z1_phase(float* smraw, const float* __restrict__ W,
        const float* __restrict__ b1, const float* __restrict__ b2){
    float (*As)[128] = (float(*)[128])smraw;
    float (*Bs)[128] = (float(*)[128])(smraw + 1024);
    int tid = threadIdx.x;
    int m0 = (blockIdx.x >> 4)*128, n0 = (blockIdx.x & 15)*128;
    int lr = tid >> 1, lc = (tid & 1)*4;
    const float* Ap = g_HS0 + (size_t)(m0 + lr)*Hh + lc;
    const float* Wp = W + (size_t)(n0 + lr)*Hh + lc;
    int tx = tid & 15, ty = tid >> 4;
    ull acc2[8][4];
    #pragma unroll
    for (int i = 0; i < 8; i++)
        #pragma unroll
        for (int j = 0; j < 4; j++) acc2[i][j] = 0ULL;
    for (int k0 = 0; k0 < Hh; k0 += 8){
        float4 av = *(const float4*)(Ap + k0);
        float4 wv = *(const float4*)(Wp + k0);
        As[lc+0][lr] = av.x; As[lc+1][lr] = av.y; As[lc+2][lr] = av.z; As[lc+3][lr] = av.w;
        Bs[lc+0][lr] = wv.x; Bs[lc+1][lr] = wv.y; Bs[lc+2][lr] = wv.z; Bs[lc+3][lr] = wv.w;
        __syncthreads();
        #pragma unroll
        for (int kk = 0; kk < 8; kk++){
            float a[8];
            *(float4*)(a)   = *(const float4*)&As[kk][ty*8];
            *(float4*)(a+4) = *(const float4*)&As[kk][ty*8+4];
            ulonglong2 bv0 = *(const ulonglong2*)&Bs[kk][tx*8];
            ulonglong2 bv1 = *(const ulonglong2*)&Bs[kk][tx*8+4];
            ull bb[4] = {bv0.x, bv0.y, bv1.x, bv1.y};
            #pragma unroll
            for (int i = 0; i < 8; i++){
                ull a2 = pk2(a[i], a[i]);
                #pragma unroll
                for (int j = 0; j < 4; j++)
                    acc2[i][j] = fma2(a2, bb[j], acc2[i][j]);
            }
        }
        __syncthreads();
    }
    #pragma unroll
    for (int i = 0; i < 8; i++){
        int m = m0 + ty*8 + i;
        #pragma unroll
        for (int j = 0; j < 4; j++){
            float2 v = upk(acc2[i][j]);
            int n = n0 + tx*8 + j*2;
            g_Z1[(size_t)m*G4 + n]     = v.x + b1[n]   + b2[n];
            g_Z1[(size_t)m*G4 + n + 1] = v.y + b1[n+1] + b2[n+1];
        }
    }
    __syncthreads();
}

// ---------------- the persistent kernel: both LSTM layers + decoder ----------------
__global__ __launch_bounds__(256, 1) void persistent_net(
    const int* __restrict__ ei,
    const float* __restrict__ gnw, const float* __restrict__ gnv, const float* __restrict__ gnb,
    const float* __restrict__ Wemb,
    const float* __restrict__ Whh0, const float* __restrict__ Whh1,
    const float* __restrict__ Wih1, const float* __restrict__ bih1, const float* __restrict__ bhh1,
    const float* __restrict__ c1Wih, const float* __restrict__ c1Whh,
    const float* __restrict__ c1bih, const float* __restrict__ c1bhh,
    const float* __restrict__ c2Wih, const float* __restrict__ c2Whh,
    const float* __restrict__ c2bih, const float* __restrict__ c2bhh,
    const float* __restrict__ Wp, const float* __restrict__ bp,
    float* __restrict__ out)
{
    __shared__ __align__(16) float sm[3456];
    int tid = threadIdx.x;
    int gtid = blockIdx.x*256 + tid;

    // zero h0,c0,h1,c1  (4*16*512 = 32768 = grid size exactly)
    g_state[gtid] = 0.f;
    gsync();

    // encoder layer 0
    for (int t = 0; t < Tt; t++){
        gemm_phase(sm, Whh0, g_state, Hh, 32, 0);
        gsync();
        reduce_phase(sm, g_Z0 + (size_t)t*Bb*G4, nullptr, nullptr, 16,
                     g_state, g_state + Bb*Hh, g_HS0 + (size_t)t*Bb*Hh);
        gsync();
    }
    // Z1 input-projection GEMM
    z1_phase(sm, Wih1, bih1, bhh1);
    gsync();
    // encoder layer 1
    for (int t = 0; t < Tt; t++){
        gemm_phase(sm, Whh1, g_state + 2*Bb*Hh, Hh, 32, 0);
        gsync();
        reduce_phase(sm, g_Z1 + (size_t)t*Bb*G4, nullptr, nullptr, 16,
                     g_state + 2*Bb*Hh, g_state + 3*Bb*Hh, nullptr);
        gsync();
    }
    // seed decoder states: (hd1,cd1)=(h0f,h0f), (hd2,cd2)=(h1f,h1f)
    if (gtid < Bb*Hh){
        float h0f = g_state[gtid];
        float h1f = g_state[2*Bb*Hh + gtid];
        g_state[4*Bb*Hh + gtid] = h0f;
        g_state[5*Bb*Hh + gtid] = h0f;
        g_state[6*Bb*Hh + gtid] = h1f;
        g_state[7*Bb*Hh + gtid] = h1f;
    }
    gsync();

    // decoder
    for (int s = 0; s < HOR; s++){
        // pred = hd2 @ Wp^T + bp  (1600 outputs, 16 lanes each over K=512)
        {
            int oid = gtid >> 4, l16 = gtid & 15;
            float v = 0.f;
            if (oid < BN){
                int b = oid / Nn, nn = oid - b*Nn;
                const float* hrow = g_state + 6*Bb*Hh + b*Hh + l16*32;
                const float* wrow = Wp + nn*Hh + l16*32;
                #pragma unroll
                for (int k = 0; k < 32; k += 4){
                    float4 hv = *(const float4*)(hrow + k);
                    float4 wv = *(const float4*)(wrow + k);
                    v += hv.x*wv.x + hv.y*wv.y + hv.z*wv.z + hv.w*wv.w;
                }
            }
            #pragma unroll
            for (int o = 8; o > 0; o >>= 1) v += __shfl_down_sync(0xffffffffu, v, o, 16);
            if (oid < BN && l16 == 0){
                int nn = oid % Nn;
                v += bp[nn];
                g_pred[oid] = v;
                out[oid*HOR + s] = v;
            }
        }
        gsync();
        // graph gather + gelu + embed -> g_xin
        if (gtid < BN){
            int b = gtid / Nn, d = gtid - b*Nn;
            float agg = 0.f;
            int i0 = g_csr_off[d], i1 = g_csr_off[d+1];
            for (int ii = i0; ii < i1; ii++){
                int e = g_csr_eid[ii];
                agg += g_norm[e] * g_pred[b*Nn + ei[e]];
            }
            float p = g_pred[gtid];
            float* dst = g_xin + b*NC + d*Cc;
            #pragma unroll
            for (int c2 = 0; c2 < Cc; c2++){
                float z = agg*gnw[c2] + p*gnv[c2] + gnb[c2];
                dst[c2] = geluf(z) + Wemb[d*Cc + c2];
            }
        }
        gsync();
        // cell 1: input (K=3200, chunks 0..15 of 200) + recurrent (K=512, chunks 16..31 of 32)
        gemm_phase(sm, c1Wih, g_xin, NC, 200, 0);
        gemm_phase(sm, c1Whh, g_state + 4*Bb*Hh, Hh, 32, 16);
        gsync();
        reduce_phase(sm, nullptr, c1bih, c1bhh, 32,
                     g_state + 4*Bb*Hh, g_state + 5*Bb*Hh, nullptr);
        gsync();
        // cell 2: input = hd1_new (K=512, chunks 0..15) + recurrent hd2 (chunks 16..31)
        gemm_phase(sm, c2Wih, g_state + 4*Bb*Hh, Hh, 32, 0);
        gemm_phase(sm, c2Whh, g_state + 6*Bb*Hh, Hh, 32, 16);
        gsync();
        reduce_phase(sm, nullptr, c2bih, c2bhh, 32,
                     g_state + 6*Bb*Hh, g_state + 7*Bb*Hh, nullptr);
        gsync();
    }
}

// ---------------- launch ----------------
extern "C" void kernel_launch(void* const* d_in, const int* in_sizes, int n_in,
                              void* d_out, int out_size){
    const float* window = (const float*)d_in[0];
    const int*   ei     = (const int*)  d_in[1];
    const float* eattr  = (const float*)d_in[2];
    const float* Wemb   = (const float*)d_in[3];
    const float* tgw    = (const float*)d_in[4];
    const float* tgv    = (const float*)d_in[5];
    const float* tgb    = (const float*)d_in[6];
    const float* gnw    = (const float*)d_in[7];
    const float* gnv    = (const float*)d_in[8];
    const float* gnb    = (const float*)d_in[9];
    const float* Wih0   = (const float*)d_in[10];
    const float* Whh0   = (const float*)d_in[11];
    const float* bih0   = (const float*)d_in[12];
    const float* bhh0   = (const float*)d_in[13];
    const float* Wih1   = (const float*)d_in[14];
    const float* Whh1   = (const float*)d_in[15];
    const float* bih1   = (const float*)d_in[16];
    const float* bhh1   = (const float*)d_in[17];
    const float* c1Wih  = (const float*)d_in[18];
    const float* c1Whh  = (const float*)d_in[19];
    const float* c1bih  = (const float*)d_in[20];
    const float* c1bhh  = (const float*)d_in[21];
    const float* c2Wih  = (const float*)d_in[22];
    const float* c2Whh  = (const float*)d_in[23];
    const float* c2bih  = (const float*)d_in[24];
    const float* c2bhh  = (const float*)d_in[25];
    const float* Wp     = (const float*)d_in[26];
    const float* bp     = (const float*)d_in[27];
    float* out = (float*)d_out;

    build_csr<<<1,128>>>(ei, eattr);
    fused_x0<<<TOTF/128,128>>>(window, ei, tgw, tgv, tgb, Wemb);
    sgemm_z0<<<dim3(16,8),256>>>(Wih0, bih0, bhh0);
    persistent_net<<<NBLK,256>>>(ei, gnw, gnv, gnb, Wemb, Whh0, Whh1,
                                 Wih1, bih1, bhh1,
                                 c1Wih, c1Whh, c1bih, c1bhh,
                                 c2Wih, c2Whh, c2bih, c2bhh,
                                 Wp, bp, out);
}

// round 10
// speedup vs baseline: 1.2130x; 1.0242x over previous
#include <cuda_runtime.h>
#include <math.h>

// Problem constants
#define Nn   100
#define Cc   32
#define Hh   512
#define Tt   64
#define Bb   16
#define Ee   2000
#define HOR  10
#define BN   1600
#define NC   3200
#define G4   2048
#define TOTF (Tt*BN)
#define NBLK 128

typedef unsigned long long ull;

// ---------------- scratch (static device memory; no allocation) ----------------
__device__ float g_X0[Tt*Bb*NC];
__device__ float g_Z0[Tt*Bb*G4];
__device__ float g_pp[48*Bb*G4];
__device__ float g_state[8*Bb*Hh];      // h0,c0,h1,c1,hd1,cd1,hd2,cd2
__device__ float g_pred[BN];
__device__ float g_xin[Bb*NC];
__device__ float g_norm[Ee];
__device__ int   g_csr_eid[Ee];
__device__ int   g_csr_off[Nn+1];
__device__ volatile unsigned g_flags[NBLK];
__device__ volatile unsigned g_rel;

// ---------------- helpers ----------------
__device__ __forceinline__ float sigf(float x){ return 1.0f/(1.0f+expf(-x)); }
__device__ __forceinline__ float geluf(float x){
    return 0.5f*x*(1.0f+erff(x*0.70710678118654752440f));
}
__device__ __forceinline__ ull pk2(float lo, float hi){
    ull r; asm("mov.b64 %0,{%1,%2};" : "=l"(r) : "f"(lo), "f"(hi)); return r;
}
__device__ __forceinline__ ull fma2(ull a, ull b, ull c){
    ull d; asm("fma.rn.f32x2 %0, %1, %2, %3;" : "=l"(d) : "l"(a), "l"(b), "l"(c)); return d;
}
__device__ __forceinline__ float2 upk(ull v){
    float2 f; asm("mov.b64 {%0,%1}, %2;" : "=f"(f.x), "=f"(f.y) : "l"(v)); return f;
}

// flag-array grid barrier: per-block flag store (no atomic serialization),
// block 0 polls all flags in parallel and releases. 128 blocks <= 148 SMs
// at 1 block/SM => co-resident, no deadlock. Monotonic gens survive graph replay.
__device__ __forceinline__ void gsync(unsigned gen){
    __syncthreads();
    if (threadIdx.x == 0){
        __threadfence();                    // drain writes + L1 inval (gpu scope)
        g_flags[blockIdx.x] = gen;
    }
    if (blockIdx.x == 0){
        if (threadIdx.x < NBLK){
            while ((int)(g_flags[threadIdx.x] - gen) < 0) { }
        }
        __syncthreads();
        if (threadIdx.x == 0){
            __threadfence();
            g_rel = gen;
        }
    } else {
        if (threadIdx.x == 0){
            while ((int)(g_rel - gen) < 0) { }
            __threadfence();                // L1 inval before consuming peers' data
        }
    }
    __syncthreads();
}

// ---------------- CSR + normalization (deterministic, one block) ----------------
__global__ void build_csr(const int* __restrict__ ei, const float* __restrict__ attr){
    __shared__ int   cols[Ee];
    __shared__ float attrs[Ee];
    __shared__ float dinv[Nn];
    __shared__ int   cnt[Nn];
    __shared__ int   offs[Nn+1];
    int tid = threadIdx.x;
    for (int e = tid; e < Ee; e += blockDim.x){
        cols[e]  = ei[Ee + e];
        attrs[e] = attr[e];
    }
    __syncthreads();
    for (int d = tid; d < Nn; d += blockDim.x){
        float dg = 0.f; int c = 0;
        for (int e = 0; e < Ee; e++){
            if (cols[e] == d){ dg += attrs[e]; c++; }
        }
        cnt[d] = c;
        dinv[d] = (dg > 0.f) ? (1.0f/sqrtf(fmaxf(dg, 1e-12f))) : 0.f;
    }
    __syncthreads();
    for (int e = tid; e < Ee; e += blockDim.x)
        g_norm[e] = dinv[ei[e]] * attrs[e] * dinv[cols[e]];
    if (tid == 0){
        offs[0] = 0;
        for (int i = 0; i < Nn; i++) offs[i+1] = offs[i] + cnt[i];
    }
    __syncthreads();
    for (int i = tid; i <= Nn; i += blockDim.x) g_csr_off[i] = offs[i];
    for (int d = tid; d < Nn; d += blockDim.x){
        int p = offs[d];
        for (int e = 0; e < Ee; e++)
            if (cols[e] == d) g_csr_eid[p++] = e;
    }
}

// ---------------- fused temporal ARMA -> gelu -> embed -> transpose ----------------
__global__ void fused_x0(const float* __restrict__ x, const int* __restrict__ ei,
                         const float* __restrict__ tw, const float* __restrict__ tv,
                         const float* __restrict__ tb, const float* __restrict__ Wemb){
    int f = blockIdx.x*blockDim.x + threadIdx.x;
    if (f >= TOTF) return;
    int tc = f / BN; int r = f - tc*BN; int bq = r / Nn; int d = r - bq*Nn;
    int base = tc*BN + bq*Nn;
    float agg = 0.f;
    int i0 = g_csr_off[d], i1 = g_csr_off[d+1];
    for (int ii = i0; ii < i1; ii++){
        int e = g_csr_eid[ii];
        agg += g_norm[e] * x[base + ei[e]];
    }
    float xi = x[f];
    int bo = f / (Nn*Tt); int rr = f - bo*(Nn*Tt); int nn = rr / Tt; int t = rr - nn*Tt;
    float* dst = g_X0 + ((size_t)(t*Bb + bo))*NC + nn*Cc;
    #pragma unroll
    for (int c2 = 0; c2 < Cc; c2++){
        float z = agg*tw[c2] + xi*tv[c2] + tb[c2];
        dst[c2] = geluf(z) + Wemb[nn*Cc + c2];
    }
}

// ---------------- Z0 GEMM (FFMA2): g_Z0 = g_X0 @ Wih0^T + bih0 + bhh0 ----------------
__global__ __launch_bounds__(256) void sgemm_z0(const float* __restrict__ W,
        const float* __restrict__ b1, const float* __restrict__ b2){
    const int K = NC;
    __shared__ __align__(16) float As[8][128];
    __shared__ __align__(16) float Bs[8][128];
    int tid = threadIdx.x;
    int m0 = blockIdx.y*128, n0 = blockIdx.x*128;
    int lr = tid >> 1, lc = (tid & 1)*4;
    const float* Ap = g_X0 + (size_t)(m0 + lr)*K + lc;
    const float* Wp = W + (size_t)(n0 + lr)*K + lc;
    int tx = tid & 15, ty = tid >> 4;
    ull acc2[8][4];
    #pragma unroll
    for (int i = 0; i < 8; i++)
        #pragma unroll
        for (int j = 0; j < 4; j++) acc2[i][j] = 0ULL;

    for (int k0 = 0; k0 < K; k0 += 8){
        float4 av = *(const float4*)(Ap + k0);
        float4 wv = *(const float4*)(Wp + k0);
        As[lc+0][lr] = av.x; As[lc+1][lr] = av.y; As[lc+2][lr] = av.z; As[lc+3][lr] = av.w;
        Bs[lc+0][lr] = wv.x; Bs[lc+1][lr] = wv.y; Bs[lc+2][lr] = wv.z; Bs[lc+3][lr] = wv.w;
        __syncthreads();
        #pragma unroll
        for (int kk = 0; kk < 8; kk++){
            float a[8];
            *(float4*)(a)   = *(const float4*)&As[kk][ty*8];
            *(float4*)(a+4) = *(const float4*)&As[kk][ty*8+4];
            ulonglong2 bv0 = *(const ulonglong2*)&Bs[kk][tx*8];
            ulonglong2 bv1 = *(const ulonglong2*)&Bs[kk][tx*8+4];
            ull bb[4] = {bv0.x, bv0.y, bv1.x, bv1.y};
            #pragma unroll
            for (int i = 0; i < 8; i++){
                ull a2 = pk2(a[i], a[i]);
                #pragma unroll
                for (int j = 0; j < 4; j++)
                    acc2[i][j] = fma2(a2, bb[j], acc2[i][j]);
            }
        }
        __syncthreads();
    }
    #pragma unroll
    for (int i = 0; i < 8; i++){
        int m = m0 + ty*8 + i;
        #pragma unroll
        for (int j = 0; j < 4; j++){
            float2 v = upk(acc2[i][j]);
            int n = n0 + tx*8 + j*2;
            g_Z0[(size_t)m*G4 + n]     = v.x + b1[n]   + b2[n];
            g_Z0[(size_t)m*G4 + n + 1] = v.y + b1[n+1] + b2[n+1];
        }
    }
}

// ---------------- persistent-kernel phases ----------------
// one K-chunk x j-tile partial GEMM: pp[slot][b][j] = sum_{k chunk} A[b][k]*W[j][k]
__device__ __forceinline__ void run_tile(float* sm, const float* __restrict__ W,
        const float* __restrict__ A, int lda, int ksz, int kc, int jt, int slot){
    int tid = threadIdx.x;
    int j = jt*256 + tid;
    int kb = kc*ksz;
    for (int i = tid; i < ksz*16; i += 256){
        int k = i >> 4, b = i & 15;
        sm[k*16 + b] = A[b*lda + kb + k];
    }
    __syncthreads();
    ull acc2[8];
    #pragma unroll
    for (int m = 0; m < 8; m++) acc2[m] = 0ULL;
    const float* wr = W + (size_t)j*lda + kb;
    for (int k = 0; k < ksz; k += 4){
        float4 w4 = *(const float4*)(wr + k);
        float wv[4] = {w4.x, w4.y, w4.z, w4.w};
        #pragma unroll
        for (int kk = 0; kk < 4; kk++){
            ull w2 = pk2(wv[kk], wv[kk]);
            const ulonglong2* hp = (const ulonglong2*)(sm + (k+kk)*16);
            ulonglong2 h0 = hp[0], h1 = hp[1], h2 = hp[2], h3 = hp[3];
            acc2[0] = fma2(w2, h0.x, acc2[0]);
            acc2[1] = fma2(w2, h0.y, acc2[1]);
            acc2[2] = fma2(w2, h1.x, acc2[2]);
            acc2[3] = fma2(w2, h1.y, acc2[3]);
            acc2[4] = fma2(w2, h2.x, acc2[4]);
            acc2[5] = fma2(w2, h2.y, acc2[5]);
            acc2[6] = fma2(w2, h3.x, acc2[6]);
            acc2[7] = fma2(w2, h3.y, acc2[7]);
        }
    }
    float* p = g_pp + (size_t)slot*(Bb*G4);
    #pragma unroll
    for (int m = 0; m < 8; m++){
        float2 v = upk(acc2[m]);
        p[(2*m  )*G4 + j] = v.x;
        p[(2*m+1)*G4 + j] = v.y;
    }
    __syncthreads();
}

// reduce partials + LSTM cell update. bid -> (bb=bid>>3, ur=bid&7), thread -> (gate,u)
__device__ __forceinline__ void reduce_phase(float* sm, const float* __restrict__ Z,
        const float* __restrict__ b1, const float* __restrict__ b2,
        int nsplit, int kcoff,
        float* __restrict__ h, float* __restrict__ c){
    int tid = threadIdx.x, bid = blockIdx.x;
    int g = tid >> 6, uo = tid & 63;
    int bb = bid >> 3, ur = bid & 7;
    int u = ur*64 + uo;
    int j = g*512 + u;
    float p = Z ? Z[bb*G4 + j] : (b1[j] + b2[j]);
    for (int kc = kcoff; kc < kcoff + nsplit; kc++)
        p += g_pp[(size_t)kc*(Bb*G4) + bb*G4 + j];
    sm[g*64 + uo] = p;
    __syncthreads();
    if (tid < 64){
        int idx = bb*Hh + ur*64 + tid;
        float ig = sigf(sm[tid]);
        float fg = sigf(sm[64 + tid]);
        float gg = tanhf(sm[128 + tid]);
        float og = sigf(sm[192 + tid]);
        float cn = fg*c[idx] + ig*gg;
        float hn = og*tanhf(cn);
        c[idx] = cn; h[idx] = hn;
    }
    __syncthreads();
}

// ---------------- the persistent kernel: wavefront 2-layer LSTM + decoder ----------------
__global__ __launch_bounds__(256, 1) void persistent_net(
    const int* __restrict__ ei,
    const float* __restrict__ gnw, const float* __restrict__ gnv, const float* __restrict__ gnb,
    const float* __restrict__ Wemb,
    const float* __restrict__ Whh0, const float* __restrict__ Whh1,
    const float* __restrict__ Wih1, const float* __restrict__ bih1, const float* __restrict__ bhh1,
    const float* __restrict__ c1Wih, const float* __restrict__ c1Whh,
    const float* __restrict__ c1bih, const float* __restrict__ c1bhh,
    const float* __restrict__ c2Wih, const float* __restrict__ c2Whh,
    const float* __restrict__ c2bih, const float* __restrict__ c2bhh,
    const float* __restrict__ Wp, const float* __restrict__ bp,
    float* __restrict__ out)
{
    __shared__ __align__(16) float sm[3456];
    int tid = threadIdx.x, bid = blockIdx.x;
    int gtid = bid*256 + tid;
    unsigned gen = g_rel;          // stable base (no release until all arrive)

    // zero h0,c0,h1,c1  (4*16*512 = 32768 = grid size exactly)
    g_state[gtid] = 0.f;
    gsync(++gen);

    // ---- wavefront encoder: superstep s runs layer0 step s and layer1 step s-1 ----
    for (int s = 0; s <= Tt; s++){
        // gemm phase (each block: up to 3 tiles)
        if (s < Tt)                 // layer0: h0 @ Whh0^T, 16 chunks of 32
            run_tile(sm, Whh0, g_state, Hh, 32, bid>>3, bid&7, bid>>3);
        if (s >= 1){                // layer1: [hs0(prev)=h0 ; h1] @ [Wih1;Whh1]^T
            run_tile(sm, Wih1, g_state,            Hh, 32, bid>>3, bid&7, 16 + (bid>>3));
            run_tile(sm, Whh1, g_state + 2*Bb*Hh,  Hh, 32, bid>>3, bid&7, 32 + (bid>>3));
        }
        gsync(++gen);
        // reduce/update phase
        if (s < Tt)
            reduce_phase(sm, g_Z0 + (size_t)s*Bb*G4, nullptr, nullptr, 16, 0,
                         g_state, g_state + Bb*Hh);
        if (s >= 1)
            reduce_phase(sm, nullptr, bih1, bhh1, 32, 16,
                         g_state + 2*Bb*Hh, g_state + 3*Bb*Hh);
        gsync(++gen);
    }

    // seed decoder states: (hd1,cd1)=(h0 final, h0 final), (hd2,cd2)=(h1 final, h1 final)
    if (gtid < Bb*Hh){
        float h0f = g_state[gtid];
        float h1f = g_state[2*Bb*Hh + gtid];
        g_state[4*Bb*Hh + gtid] = h0f;
        g_state[5*Bb*Hh + gtid] = h0f;
        g_state[6*Bb*Hh + gtid] = h1f;
        g_state[7*Bb*Hh + gtid] = h1f;
    }
    gsync(++gen);

    // ---- decoder ----
    for (int s = 0; s < HOR; s++){
        // pred = hd2 @ Wp^T + bp  (1600 outputs, 16 lanes each over K=512)
        {
            int oid = gtid >> 4, l16 = gtid & 15;
            float v = 0.f;
            if (oid < BN){
                int b = oid / Nn, nn = oid - b*Nn;
                const float* hrow = g_state + 6*Bb*Hh + b*Hh + l16*32;
                const float* wrow = Wp + nn*Hh + l16*32;
                #pragma unroll
                for (int k = 0; k < 32; k += 4){
                    float4 hv = *(const float4*)(hrow + k);
                    float4 wv = *(const float4*)(wrow + k);
                    v += hv.x*wv.x + hv.y*wv.y + hv.z*wv.z + hv.w*wv.w;
                }
            }
            #pragma unroll
            for (int o = 8; o > 0; o >>= 1) v += __shfl_down_sync(0xffffffffu, v, o, 16);
            if (oid < BN && l16 == 0){
                int nn = oid % Nn;
                v += bp[nn];
                g_pred[oid] = v;
                out[oid*HOR + s] = v;
            }
        }
        gsync(++gen);
        // graph gather + gelu + embed -> g_xin
        if (gtid < BN){
            int b = gtid / Nn, d = gtid - b*Nn;
            float agg = 0.f;
            int i0 = g_csr_off[d], i1 = g_csr_off[d+1];
            for (int ii = i0; ii < i1; ii++){
                int e = g_csr_eid[ii];
                agg += g_norm[e] * g_pred[b*Nn + ei[e]];
            }
            float p = g_pred[gtid];
            float* dst = g_xin + b*NC + d*Cc;
            #pragma unroll
            for (int c2 = 0; c2 < Cc; c2++){
                float z = agg*gnw[c2] + p*gnv[c2] + gnb[c2];
                dst[c2] = geluf(z) + Wemb[d*Cc + c2];
            }
        }
        gsync(++gen);
        // cell 1: input (K=3200, 16 chunks of 200) + recurrent (K=512, 16 chunks of 32)
        run_tile(sm, c1Wih, g_xin,             NC, 200, bid>>3, bid&7, bid>>3);
        run_tile(sm, c1Whh, g_state + 4*Bb*Hh, Hh, 32,  bid>>3, bid&7, 16 + (bid>>3));
        gsync(++gen);
        reduce_phase(sm, nullptr, c1bih, c1bhh, 32, 0,
                     g_state + 4*Bb*Hh, g_state + 5*Bb*Hh);
        gsync(++gen);
        // cell 2: input = hd1_new (K=512) + recurrent hd2 (K=512)
        run_tile(sm, c2Wih, g_state + 4*Bb*Hh, Hh, 32, bid>>3, bid&7, bid>>3);
        run_tile(sm, c2Whh, g_state + 6*Bb*Hh, Hh, 32, bid>>3, bid&7, 16 + (bid>>3));
        gsync(++gen);
        reduce_phase(sm, nullptr, c2bih, c2bhh, 32, 0,
                     g_state + 6*Bb*Hh, g_state + 7*Bb*Hh);
        gsync(++gen);
    }
}

// ---------------- launch ----------------
extern "C" void kernel_launch(void* const* d_in, const int* in_sizes, int n_in,
                              void* d_out, int out_size){
    const float* window = (const float*)d_in[0];
    const int*   ei     = (const int*)  d_in[1];
    const float* eattr  = (const float*)d_in[2];
    const float* Wemb   = (const float*)d_in[3];
    const float* tgw    = (const float*)d_in[4];
    const float* tgv    = (const float*)d_in[5];
    const float* tgb    = (const float*)d_in[6];
    const float* gnw    = (const float*)d_in[7];
    const float* gnv    = (const float*)d_in[8];
    const float* gnb    = (const float*)d_in[9];
    const float* Wih0   = (const float*)d_in[10];
    const float* Whh0   = (const float*)d_in[11];
    const float* bih0   = (const float*)d_in[12];
    const float* bhh0   = (const float*)d_in[13];
    const float* Wih1   = (const float*)d_in[14];
    const float* Whh1   = (const float*)d_in[15];
    const float* bih1   = (const float*)d_in[16];
    const float* bhh1   = (const float*)d_in[17];
    const float* c1Wih  = (const float*)d_in[18];
    const float* c1Whh  = (const float*)d_in[19];
    const float* c1bih  = (const float*)d_in[20];
    const float* c1bhh  = (const float*)d_in[21];
    const float* c2Wih  = (const float*)d_in[22];
    const float* c2Whh  = (const float*)d_in[23];
    const float* c2bih  = (const float*)d_in[24];
    const float* c2bhh  = (const float*)d_in[25];
    const float* Wp     = (const float*)d_in[26];
    const float* bp     = (const float*)d_in[27];
    float* out = (float*)d_out;

    build_csr<<<1,128>>>(ei, eattr);
    fused_x0<<<TOTF/128,128>>>(window, ei, tgw, tgv, tgb, Wemb);
    sgemm_z0<<<dim3(16,8),256>>>(Wih0, bih0, bhh0);
    persistent_net<<<NBLK,256>>>(ei, gnw, gnv, gnb, Wemb, Whh0, Whh1,
                                 Wih1, bih1, bhh1,
                                 c1Wih, c1Whh, c1bih, c1bhh,
                                 c2Wih, c2Whh, c2bih, c2bhh,
                                 Wp, bp, out);
}